// round 1
// baseline (speedup 1.0000x reference)
#include <cuda_runtime.h>
#include <math.h>

// Problem constants
#define BB   2
#define LL   2048
#define DD   2048
#define HH   16
#define KVH  4
#define EE   128
#define ML   (BB*LL)        // 4096 rows total
#define HE   (HH*EE)        // 2048
#define KVE  (KVH*EE)       // 512

// -------- scratch (device globals; no allocation allowed) --------
__device__ float g_Q[ML*HE];      // [B*L, H*E]
__device__ float g_K[ML*KVE];     // [B*L, KV*E]
__device__ float g_V[ML*KVE];     // [B*L, KV*E]
__device__ float g_CTX[ML*HE];    // attention output
__device__ float g_Y[ML*DD];      // pre-GELU O-proj output

// ============================================================
// SGEMM: C[M,N] = A[M,K] @ B[K,N] + bias[N]   (row-major all)
// 128x128 block tile, BK=8, 256 threads, 8x8 per thread.
// Requires M%128==0, N%128==0, K%8==0 (true for all our shapes).
// ============================================================
__global__ __launch_bounds__(256)
void sgemm_bias(const float* __restrict__ A, const float* __restrict__ B,
                const float* __restrict__ bias, float* __restrict__ C,
                int M, int N, int K)
{
    __shared__ float As[8][128];   // transposed A tile: As[k][m]
    __shared__ float Bs[8][128];   // Bs[k][n]

    const int tid = threadIdx.x;
    const int bx = blockIdx.x, by = blockIdx.y;
    const int tx = tid & 15, ty = tid >> 4;

    const int a_r = tid >> 1, a_c = (tid & 1) * 4;      // A: 128 rows x 8 cols (float4)
    const int b_r = tid >> 5, b_c = (tid & 31) * 4;     // B: 8 rows x 128 cols (float4)

    const float* Ag = A + ((size_t)(by*128 + a_r))*K + a_c;
    const float* Bg = B + (size_t)b_r*N + bx*128 + b_c;

    float acc[8][8];
    #pragma unroll
    for (int a = 0; a < 8; a++)
        #pragma unroll
        for (int b2 = 0; b2 < 8; b2++) acc[a][b2] = 0.f;

    for (int k0 = 0; k0 < K; k0 += 8) {
        float4 av = *(const float4*)(Ag + k0);
        As[a_c+0][a_r] = av.x;
        As[a_c+1][a_r] = av.y;
        As[a_c+2][a_r] = av.z;
        As[a_c+3][a_r] = av.w;
        *(float4*)&Bs[b_r][b_c] = *(const float4*)(Bg + (size_t)k0*N);
        __syncthreads();

        #pragma unroll
        for (int k = 0; k < 8; ++k) {
            float ar[8], br[8];
            *(float4*)(ar)   = *(float4*)&As[k][ty*8];
            *(float4*)(ar+4) = *(float4*)&As[k][ty*8+4];
            *(float4*)(br)   = *(float4*)&Bs[k][tx*8];
            *(float4*)(br+4) = *(float4*)&Bs[k][tx*8+4];
            #pragma unroll
            for (int a = 0; a < 8; a++)
                #pragma unroll
                for (int b2 = 0; b2 < 8; b2++)
                    acc[a][b2] += ar[a]*br[b2];
        }
        __syncthreads();
    }

    #pragma unroll
    for (int a = 0; a < 8; a++) {
        const int row = by*128 + ty*8 + a;
        #pragma unroll
        for (int b2 = 0; b2 < 8; b2 += 4) {
            const int col = bx*128 + tx*8 + b2;
            float4 o;
            o.x = acc[a][b2+0] + bias[col+0];
            o.y = acc[a][b2+1] + bias[col+1];
            o.z = acc[a][b2+2] + bias[col+2];
            o.w = acc[a][b2+3] + bias[col+3];
            *(float4*)(C + (size_t)row*N + col) = o;
        }
    }
}

// ============================================================
// Flash attention (causal, GQA): per block = one (b,h) x 64-query tile.
// Br=Bc=64, E=128. Online softmax, O in registers (4 rows x 8 cols / thread).
// ============================================================
#define FL_SMEM_FLOATS (64*128 + 128*68 + 64*128 + 64*68 + 192)

__global__ __launch_bounds__(256)
void flash_kernel(const float* __restrict__ Q, const float* __restrict__ K,
                  const float* __restrict__ V, float* __restrict__ ctx)
{
    extern __shared__ float sm[];
    float* Qs  = sm;                  // [64][128]  scaled Q
    float* Kst = Qs  + 64*128;        // [128][68]  K transposed (e-major), padded
    float* Vs  = Kst + 128*68;        // [64][128]
    float* Ss  = Vs  + 64*128;        // [64][68]   scores / probabilities
    float* mrow = Ss + 64*68;         // [64]
    float* lrow = mrow + 64;          // [64]
    float* arow = lrow + 64;          // [64]

    const int tid = threadIdx.x;
    const int bh  = blockIdx.y;
    const int b   = bh / HH, h = bh % HH;
    const int kv  = h % KVH;                 // GQA: head h reads kv-head h%KV
    const int qb  = blockIdx.x * 64;
    const float scale = 0.08838834764831845f;   // 1/sqrt(128)

    // load Q tile (pre-scaled)
    {
        const float* Qg = Q + ((size_t)(b*LL + qb))*HE + h*EE;
        for (int t = tid; t < 64*32; t += 256) {
            int r = t >> 5, c4 = (t & 31) << 2;
            float4 v = *(const float4*)(Qg + (size_t)r*HE + c4);
            v.x *= scale; v.y *= scale; v.z *= scale; v.w *= scale;
            *(float4*)(Qs + r*128 + c4) = v;
        }
    }
    if (tid < 64) { mrow[tid] = -INFINITY; lrow[tid] = 0.f; }

    float O[4][8];
    #pragma unroll
    for (int a = 0; a < 4; a++)
        #pragma unroll
        for (int e = 0; e < 8; e++) O[a][e] = 0.f;

    const int i = tid >> 4, j = tid & 15;   // 16x16 thread grid
    const int r0 = i*4;                     // 4 query rows per thread
    const int c0 = j*4;                     // 4 key cols (S phase)
    const int e0 = j*8;                     // 8 head dims (O phase)

    const int ntiles = qb/64 + 1;           // causal
    for (int tkv = 0; tkv < ntiles; ++tkv) {
        const int kb = tkv * 64;
        __syncthreads();   // protect smem reuse across iterations (and Q load, 1st iter)

        // load K (transposed into Kst[e][c]) and V (row-major)
        const float* Kg = K + ((size_t)(b*LL + kb))*KVE + kv*EE;
        const float* Vg = V + ((size_t)(b*LL + kb))*KVE + kv*EE;
        for (int t = tid; t < 64*32; t += 256) {
            int r = t >> 5, c4 = (t & 31) << 2;
            float4 vk = *(const float4*)(Kg + (size_t)r*KVE + c4);
            Kst[(c4+0)*68 + r] = vk.x;
            Kst[(c4+1)*68 + r] = vk.y;
            Kst[(c4+2)*68 + r] = vk.z;
            Kst[(c4+3)*68 + r] = vk.w;
            *(float4*)(Vs + r*128 + c4) = *(const float4*)(Vg + (size_t)r*KVE + c4);
        }
        __syncthreads();

        // S = (Q*scale) @ K^T : each thread computes a 4x4 block
        float acc[4][4];
        #pragma unroll
        for (int a = 0; a < 4; a++)
            #pragma unroll
            for (int c = 0; c < 4; c++) acc[a][c] = 0.f;

        #pragma unroll 4
        for (int e = 0; e < 128; ++e) {
            const float q0 = Qs[(r0+0)*128 + e];
            const float q1 = Qs[(r0+1)*128 + e];
            const float q2 = Qs[(r0+2)*128 + e];
            const float q3 = Qs[(r0+3)*128 + e];
            const float4 kvv = *(const float4*)(Kst + e*68 + c0);
            acc[0][0] += q0*kvv.x; acc[0][1] += q0*kvv.y; acc[0][2] += q0*kvv.z; acc[0][3] += q0*kvv.w;
            acc[1][0] += q1*kvv.x; acc[1][1] += q1*kvv.y; acc[1][2] += q1*kvv.z; acc[1][3] += q1*kvv.w;
            acc[2][0] += q2*kvv.x; acc[2][1] += q2*kvv.y; acc[2][2] += q2*kvv.z; acc[2][3] += q2*kvv.w;
            acc[3][0] += q3*kvv.x; acc[3][1] += q3*kvv.y; acc[3][2] += q3*kvv.z; acc[3][3] += q3*kvv.w;
        }

        const bool diag = (kb == qb);
        #pragma unroll
        for (int a = 0; a < 4; a++)
            #pragma unroll
            for (int c = 0; c < 4; c++) {
                float v = acc[a][c];
                if (diag && (c0 + c) > (r0 + a)) v = -1e30f;
                Ss[(r0+a)*68 + c0 + c] = v;
            }
        __syncthreads();

        // online softmax per row (64 threads)
        if (tid < 64) {
            const int r = tid;
            float mx = -1e30f;
            #pragma unroll 8
            for (int c = 0; c < 64; ++c) mx = fmaxf(mx, Ss[r*68 + c]);
            const float mold = mrow[r];
            const float mnew = fmaxf(mold, mx);
            const float al   = __expf(mold - mnew);   // 0 on first tile
            float s = 0.f;
            #pragma unroll 8
            for (int c = 0; c < 64; ++c) {
                float p = __expf(Ss[r*68 + c] - mnew);
                Ss[r*68 + c] = p;
                s += p;
            }
            mrow[r] = mnew;
            lrow[r] = lrow[r]*al + s;
            arow[r] = al;
        }
        __syncthreads();

        // O = O*alpha + P @ V
        const float al0 = arow[r0+0], al1 = arow[r0+1], al2 = arow[r0+2], al3 = arow[r0+3];
        #pragma unroll
        for (int e = 0; e < 8; e++) {
            O[0][e] *= al0; O[1][e] *= al1; O[2][e] *= al2; O[3][e] *= al3;
        }
        #pragma unroll 2
        for (int c = 0; c < 64; ++c) {
            const float p0 = Ss[(r0+0)*68 + c];
            const float p1 = Ss[(r0+1)*68 + c];
            const float p2 = Ss[(r0+2)*68 + c];
            const float p3 = Ss[(r0+3)*68 + c];
            const float4 va = *(const float4*)(Vs + c*128 + e0);
            const float4 vb = *(const float4*)(Vs + c*128 + e0 + 4);
            O[0][0]+=p0*va.x; O[0][1]+=p0*va.y; O[0][2]+=p0*va.z; O[0][3]+=p0*va.w;
            O[0][4]+=p0*vb.x; O[0][5]+=p0*vb.y; O[0][6]+=p0*vb.z; O[0][7]+=p0*vb.w;
            O[1][0]+=p1*va.x; O[1][1]+=p1*va.y; O[1][2]+=p1*va.z; O[1][3]+=p1*va.w;
            O[1][4]+=p1*vb.x; O[1][5]+=p1*vb.y; O[1][6]+=p1*vb.z; O[1][7]+=p1*vb.w;
            O[2][0]+=p2*va.x; O[2][1]+=p2*va.y; O[2][2]+=p2*va.z; O[2][3]+=p2*va.w;
            O[2][4]+=p2*vb.x; O[2][5]+=p2*vb.y; O[2][6]+=p2*vb.z; O[2][7]+=p2*vb.w;
            O[3][0]+=p3*va.x; O[3][1]+=p3*va.y; O[3][2]+=p3*va.z; O[3][3]+=p3*va.w;
            O[3][4]+=p3*vb.x; O[3][5]+=p3*vb.y; O[3][6]+=p3*vb.z; O[3][7]+=p3*vb.w;
        }
    }

    // write out ctx (divide by l)
    float* Cg = ctx + ((size_t)(b*LL + qb))*HE + h*EE;
    #pragma unroll
    for (int a = 0; a < 4; a++) {
        const float inv = 1.f / lrow[r0+a];
        float4 oa, ob;
        oa.x = O[a][0]*inv; oa.y = O[a][1]*inv; oa.z = O[a][2]*inv; oa.w = O[a][3]*inv;
        ob.x = O[a][4]*inv; ob.y = O[a][5]*inv; ob.z = O[a][6]*inv; ob.w = O[a][7]*inv;
        *(float4*)(Cg + (size_t)(r0+a)*HE + e0)     = oa;
        *(float4*)(Cg + (size_t)(r0+a)*HE + e0 + 4) = ob;
    }
}

// ============================================================
// Epilogue: out = LayerNorm(x + gelu_erf(ypre)) * gamma + beta
// One block per row, 256 threads, 8 elements/thread (D=2048).
// ============================================================
__global__ __launch_bounds__(256)
void epilogue_ln(const float* __restrict__ x, const float* __restrict__ ypre,
                 const float* __restrict__ gamma, const float* __restrict__ beta,
                 float* __restrict__ out)
{
    const int row = blockIdx.x;
    const int tid = threadIdx.x;
    const float* xr = x    + (size_t)row*DD;
    const float* yr = ypre + (size_t)row*DD;
    float* outr     = out  + (size_t)row*DD;

    float vals[8];
    float s = 0.f, s2 = 0.f;
    #pragma unroll
    for (int k = 0; k < 8; ++k) {
        const int c = tid + k*256;
        const float v = yr[c];
        const float g = 0.5f*v*(1.f + erff(v*0.70710678118654752f));
        const float r = xr[c] + g;
        vals[k] = r;
        s += r; s2 += r*r;
    }

    // block reduce (8 warps)
    __shared__ float red[2][8];
    #pragma unroll
    for (int off = 16; off > 0; off >>= 1) {
        s  += __shfl_down_sync(0xFFFFFFFFu, s,  off);
        s2 += __shfl_down_sync(0xFFFFFFFFu, s2, off);
    }
    if ((tid & 31) == 0) { red[0][tid>>5] = s; red[1][tid>>5] = s2; }
    __syncthreads();
    float ts = 0.f, ts2 = 0.f;
    #pragma unroll
    for (int w = 0; w < 8; w++) { ts += red[0][w]; ts2 += red[1][w]; }

    const float mean = ts * (1.f/2048.f);
    const float var  = ts2 * (1.f/2048.f) - mean*mean;
    const float inv  = rsqrtf(var + 1e-5f);

    #pragma unroll
    for (int k = 0; k < 8; ++k) {
        const int c = tid + k*256;
        outr[c] = (vals[k] - mean)*inv*gamma[c] + beta[c];
    }
}

// ============================================================
// Launch
// ============================================================
extern "C" void kernel_launch(void* const* d_in, const int* in_sizes, int n_in,
                              void* d_out, int out_size)
{
    const float* x     = (const float*)d_in[0];
    const float* Wq    = (const float*)d_in[1];
    const float* bq    = (const float*)d_in[2];
    const float* Wk    = (const float*)d_in[3];
    const float* bk    = (const float*)d_in[4];
    const float* Wv    = (const float*)d_in[5];
    const float* bv    = (const float*)d_in[6];
    const float* Wo    = (const float*)d_in[7];
    const float* bo    = (const float*)d_in[8];
    const float* gamma = (const float*)d_in[9];
    const float* beta  = (const float*)d_in[10];
    float* out = (float*)d_out;

    float *Q, *K, *V, *CTX, *Y;
    cudaGetSymbolAddress((void**)&Q,   g_Q);
    cudaGetSymbolAddress((void**)&K,   g_K);
    cudaGetSymbolAddress((void**)&V,   g_V);
    cudaGetSymbolAddress((void**)&CTX, g_CTX);
    cudaGetSymbolAddress((void**)&Y,   g_Y);

    const dim3 blk(256);

    // QKV projections
    sgemm_bias<<<dim3(HE/128,  ML/128), blk>>>(x, Wq, bq, Q, ML, HE,  DD);
    sgemm_bias<<<dim3(KVE/128, ML/128), blk>>>(x, Wk, bk, K, ML, KVE, DD);
    sgemm_bias<<<dim3(KVE/128, ML/128), blk>>>(x, Wv, bv, V, ML, KVE, DD);

    // causal GQA flash attention
    const size_t fl_smem = (size_t)FL_SMEM_FLOATS * sizeof(float);
    cudaFuncSetAttribute(flash_kernel, cudaFuncAttributeMaxDynamicSharedMemorySize,
                         (int)fl_smem);
    flash_kernel<<<dim3(LL/64, BB*HH), blk, fl_smem>>>(Q, K, V, CTX);

    // output projection (pre-GELU)
    sgemm_bias<<<dim3(DD/128, ML/128), blk>>>(CTX, Wo, bo, Y, ML, DD, HE);

    // GELU + residual + LayerNorm
    epilogue_ln<<<ML, 256>>>(x, Y, gamma, beta, out);
}

// round 2
// speedup vs baseline: 1.0013x; 1.0013x over previous
#include <cuda_runtime.h>
#include <math.h>

// Problem constants
#define BB   2
#define LL   2048
#define DD   2048
#define HH   16
#define KVH  4
#define EE   128
#define ML   (BB*LL)        // 4096 rows total
#define HE   (HH*EE)        // 2048
#define KVE  (KVH*EE)       // 512

// -------- scratch (device globals; no allocation allowed) --------
__device__ float g_Q[ML*HE];      // [B*L, H*E]
__device__ float g_K[ML*KVE];     // [B*L, KV*E]
__device__ float g_V[ML*KVE];     // [B*L, KV*E]
__device__ float g_CTX[ML*HE];    // attention output
__device__ float g_Y[ML*DD];      // pre-GELU O-proj output

// ============================================================
// SGEMM: C[M,N] = A[M,K] @ B[K,N] + bias[N]   (row-major all)
// 128x128 block tile, BK=8, 256 threads, 8x8 per thread.
// Requires M%128==0, N%128==0, K%8==0 (true for all our shapes).
// ============================================================
__global__ __launch_bounds__(256)
void sgemm_bias(const float* __restrict__ A, const float* __restrict__ B,
                const float* __restrict__ bias, float* __restrict__ C,
                int M, int N, int K)
{
    __shared__ float As[8][128];   // transposed A tile: As[k][m]
    __shared__ float Bs[8][128];   // Bs[k][n]

    const int tid = threadIdx.x;
    const int bx = blockIdx.x, by = blockIdx.y;
    const int tx = tid & 15, ty = tid >> 4;

    const int a_r = tid >> 1, a_c = (tid & 1) * 4;      // A: 128 rows x 8 cols (float4)
    const int b_r = tid >> 5, b_c = (tid & 31) * 4;     // B: 8 rows x 128 cols (float4)

    const float* Ag = A + ((size_t)(by*128 + a_r))*K + a_c;
    const float* Bg = B + (size_t)b_r*N + bx*128 + b_c;

    float acc[8][8];
    #pragma unroll
    for (int a = 0; a < 8; a++)
        #pragma unroll
        for (int b2 = 0; b2 < 8; b2++) acc[a][b2] = 0.f;

    for (int k0 = 0; k0 < K; k0 += 8) {
        float4 av = *(const float4*)(Ag + k0);
        As[a_c+0][a_r] = av.x;
        As[a_c+1][a_r] = av.y;
        As[a_c+2][a_r] = av.z;
        As[a_c+3][a_r] = av.w;
        *(float4*)&Bs[b_r][b_c] = *(const float4*)(Bg + (size_t)k0*N);
        __syncthreads();

        #pragma unroll
        for (int k = 0; k < 8; ++k) {
            float ar[8], br[8];
            *(float4*)(ar)   = *(float4*)&As[k][ty*8];
            *(float4*)(ar+4) = *(float4*)&As[k][ty*8+4];
            *(float4*)(br)   = *(float4*)&Bs[k][tx*8];
            *(float4*)(br+4) = *(float4*)&Bs[k][tx*8+4];
            #pragma unroll
            for (int a = 0; a < 8; a++)
                #pragma unroll
                for (int b2 = 0; b2 < 8; b2++)
                    acc[a][b2] += ar[a]*br[b2];
        }
        __syncthreads();
    }

    #pragma unroll
    for (int a = 0; a < 8; a++) {
        const int row = by*128 + ty*8 + a;
        #pragma unroll
        for (int b2 = 0; b2 < 8; b2 += 4) {
            const int col = bx*128 + tx*8 + b2;
            float4 o;
            o.x = acc[a][b2+0] + bias[col+0];
            o.y = acc[a][b2+1] + bias[col+1];
            o.z = acc[a][b2+2] + bias[col+2];
            o.w = acc[a][b2+3] + bias[col+3];
            *(float4*)(C + (size_t)row*N + col) = o;
        }
    }
}

// ============================================================
// Flash attention (causal, GQA): per block = one (b,h) x 64-query tile.
// Br=Bc=64, E=128. Online softmax, O in registers (4 rows x 8 cols / thread).
// ============================================================
#define FL_SMEM_FLOATS (64*128 + 128*68 + 64*128 + 64*68 + 192)

__global__ __launch_bounds__(256)
void flash_kernel(const float* __restrict__ Q, const float* __restrict__ K,
                  const float* __restrict__ V, float* __restrict__ ctx)
{
    extern __shared__ float sm[];
    float* Qs  = sm;                  // [64][128]  scaled Q
    float* Kst = Qs  + 64*128;        // [128][68]  K transposed (e-major), padded
    float* Vs  = Kst + 128*68;        // [64][128]
    float* Ss  = Vs  + 64*128;        // [64][68]   scores / probabilities
    float* mrow = Ss + 64*68;         // [64]
    float* lrow = mrow + 64;          // [64]
    float* arow = lrow + 64;          // [64]

    const int tid = threadIdx.x;
    const int bh  = blockIdx.y;
    const int b   = bh / HH, h = bh % HH;
    const int kv  = h % KVH;                 // GQA: head h reads kv-head h%KV
    const int qb  = blockIdx.x * 64;
    const float scale = 0.08838834764831845f;   // 1/sqrt(128)

    // load Q tile (pre-scaled)
    {
        const float* Qg = Q + ((size_t)(b*LL + qb))*HE + h*EE;
        for (int t = tid; t < 64*32; t += 256) {
            int r = t >> 5, c4 = (t & 31) << 2;
            float4 v = *(const float4*)(Qg + (size_t)r*HE + c4);
            v.x *= scale; v.y *= scale; v.z *= scale; v.w *= scale;
            *(float4*)(Qs + r*128 + c4) = v;
        }
    }
    if (tid < 64) { mrow[tid] = -INFINITY; lrow[tid] = 0.f; }

    float O[4][8];
    #pragma unroll
    for (int a = 0; a < 4; a++)
        #pragma unroll
        for (int e = 0; e < 8; e++) O[a][e] = 0.f;

    const int i = tid >> 4, j = tid & 15;   // 16x16 thread grid
    const int r0 = i*4;                     // 4 query rows per thread
    const int c0 = j*4;                     // 4 key cols (S phase)
    const int e0 = j*8;                     // 8 head dims (O phase)

    const int ntiles = qb/64 + 1;           // causal
    for (int tkv = 0; tkv < ntiles; ++tkv) {
        const int kb = tkv * 64;
        __syncthreads();   // protect smem reuse across iterations (and Q load, 1st iter)

        // load K (transposed into Kst[e][c]) and V (row-major)
        const float* Kg = K + ((size_t)(b*LL + kb))*KVE + kv*EE;
        const float* Vg = V + ((size_t)(b*LL + kb))*KVE + kv*EE;
        for (int t = tid; t < 64*32; t += 256) {
            int r = t >> 5, c4 = (t & 31) << 2;
            float4 vk = *(const float4*)(Kg + (size_t)r*KVE + c4);
            Kst[(c4+0)*68 + r] = vk.x;
            Kst[(c4+1)*68 + r] = vk.y;
            Kst[(c4+2)*68 + r] = vk.z;
            Kst[(c4+3)*68 + r] = vk.w;
            *(float4*)(Vs + r*128 + c4) = *(const float4*)(Vg + (size_t)r*KVE + c4);
        }
        __syncthreads();

        // S = (Q*scale) @ K^T : each thread computes a 4x4 block
        float acc[4][4];
        #pragma unroll
        for (int a = 0; a < 4; a++)
            #pragma unroll
            for (int c = 0; c < 4; c++) acc[a][c] = 0.f;

        #pragma unroll 4
        for (int e = 0; e < 128; ++e) {
            const float q0 = Qs[(r0+0)*128 + e];
            const float q1 = Qs[(r0+1)*128 + e];
            const float q2 = Qs[(r0+2)*128 + e];
            const float q3 = Qs[(r0+3)*128 + e];
            const float4 kvv = *(const float4*)(Kst + e*68 + c0);
            acc[0][0] += q0*kvv.x; acc[0][1] += q0*kvv.y; acc[0][2] += q0*kvv.z; acc[0][3] += q0*kvv.w;
            acc[1][0] += q1*kvv.x; acc[1][1] += q1*kvv.y; acc[1][2] += q1*kvv.z; acc[1][3] += q1*kvv.w;
            acc[2][0] += q2*kvv.x; acc[2][1] += q2*kvv.y; acc[2][2] += q2*kvv.z; acc[2][3] += q2*kvv.w;
            acc[3][0] += q3*kvv.x; acc[3][1] += q3*kvv.y; acc[3][2] += q3*kvv.z; acc[3][3] += q3*kvv.w;
        }

        const bool diag = (kb == qb);
        #pragma unroll
        for (int a = 0; a < 4; a++)
            #pragma unroll
            for (int c = 0; c < 4; c++) {
                float v = acc[a][c];
                if (diag && (c0 + c) > (r0 + a)) v = -1e30f;
                Ss[(r0+a)*68 + c0 + c] = v;
            }
        __syncthreads();

        // online softmax per row (64 threads)
        if (tid < 64) {
            const int r = tid;
            float mx = -1e30f;
            #pragma unroll 8
            for (int c = 0; c < 64; ++c) mx = fmaxf(mx, Ss[r*68 + c]);
            const float mold = mrow[r];
            const float mnew = fmaxf(mold, mx);
            const float al   = __expf(mold - mnew);   // 0 on first tile
            float s = 0.f;
            #pragma unroll 8
            for (int c = 0; c < 64; ++c) {
                float p = __expf(Ss[r*68 + c] - mnew);
                Ss[r*68 + c] = p;
                s += p;
            }
            mrow[r] = mnew;
            lrow[r] = lrow[r]*al + s;
            arow[r] = al;
        }
        __syncthreads();

        // O = O*alpha + P @ V
        const float al0 = arow[r0+0], al1 = arow[r0+1], al2 = arow[r0+2], al3 = arow[r0+3];
        #pragma unroll
        for (int e = 0; e < 8; e++) {
            O[0][e] *= al0; O[1][e] *= al1; O[2][e] *= al2; O[3][e] *= al3;
        }
        #pragma unroll 2
        for (int c = 0; c < 64; ++c) {
            const float p0 = Ss[(r0+0)*68 + c];
            const float p1 = Ss[(r0+1)*68 + c];
            const float p2 = Ss[(r0+2)*68 + c];
            const float p3 = Ss[(r0+3)*68 + c];
            const float4 va = *(const float4*)(Vs + c*128 + e0);
            const float4 vb = *(const float4*)(Vs + c*128 + e0 + 4);
            O[0][0]+=p0*va.x; O[0][1]+=p0*va.y; O[0][2]+=p0*va.z; O[0][3]+=p0*va.w;
            O[0][4]+=p0*vb.x; O[0][5]+=p0*vb.y; O[0][6]+=p0*vb.z; O[0][7]+=p0*vb.w;
            O[1][0]+=p1*va.x; O[1][1]+=p1*va.y; O[1][2]+=p1*va.z; O[1][3]+=p1*va.w;
            O[1][4]+=p1*vb.x; O[1][5]+=p1*vb.y; O[1][6]+=p1*vb.z; O[1][7]+=p1*vb.w;
            O[2][0]+=p2*va.x; O[2][1]+=p2*va.y; O[2][2]+=p2*va.z; O[2][3]+=p2*va.w;
            O[2][4]+=p2*vb.x; O[2][5]+=p2*vb.y; O[2][6]+=p2*vb.z; O[2][7]+=p2*vb.w;
            O[3][0]+=p3*va.x; O[3][1]+=p3*va.y; O[3][2]+=p3*va.z; O[3][3]+=p3*va.w;
            O[3][4]+=p3*vb.x; O[3][5]+=p3*vb.y; O[3][6]+=p3*vb.z; O[3][7]+=p3*vb.w;
        }
    }

    // write out ctx (divide by l)
    float* Cg = ctx + ((size_t)(b*LL + qb))*HE + h*EE;
    #pragma unroll
    for (int a = 0; a < 4; a++) {
        const float inv = 1.f / lrow[r0+a];
        float4 oa, ob;
        oa.x = O[a][0]*inv; oa.y = O[a][1]*inv; oa.z = O[a][2]*inv; oa.w = O[a][3]*inv;
        ob.x = O[a][4]*inv; ob.y = O[a][5]*inv; ob.z = O[a][6]*inv; ob.w = O[a][7]*inv;
        *(float4*)(Cg + (size_t)(r0+a)*HE + e0)     = oa;
        *(float4*)(Cg + (size_t)(r0+a)*HE + e0 + 4) = ob;
    }
}

// ============================================================
// Epilogue: out = LayerNorm(x + gelu_erf(ypre)) * gamma + beta
// One block per row, 256 threads, 8 elements/thread (D=2048).
// ============================================================
__global__ __launch_bounds__(256)
void epilogue_ln(const float* __restrict__ x, const float* __restrict__ ypre,
                 const float* __restrict__ gamma, const float* __restrict__ beta,
                 float* __restrict__ out)
{
    const int row = blockIdx.x;
    const int tid = threadIdx.x;
    const float* xr = x    + (size_t)row*DD;
    const float* yr = ypre + (size_t)row*DD;
    float* outr     = out  + (size_t)row*DD;

    float vals[8];
    float s = 0.f, s2 = 0.f;
    #pragma unroll
    for (int k = 0; k < 8; ++k) {
        const int c = tid + k*256;
        const float v = yr[c];
        const float g = 0.5f*v*(1.f + erff(v*0.70710678118654752f));
        const float r = xr[c] + g;
        vals[k] = r;
        s += r; s2 += r*r;
    }

    // block reduce (8 warps)
    __shared__ float red[2][8];
    #pragma unroll
    for (int off = 16; off > 0; off >>= 1) {
        s  += __shfl_down_sync(0xFFFFFFFFu, s,  off);
        s2 += __shfl_down_sync(0xFFFFFFFFu, s2, off);
    }
    if ((tid & 31) == 0) { red[0][tid>>5] = s; red[1][tid>>5] = s2; }
    __syncthreads();
    float ts = 0.f, ts2 = 0.f;
    #pragma unroll
    for (int w = 0; w < 8; w++) { ts += red[0][w]; ts2 += red[1][w]; }

    const float mean = ts * (1.f/2048.f);
    const float var  = ts2 * (1.f/2048.f) - mean*mean;
    const float inv  = rsqrtf(var + 1e-5f);

    #pragma unroll
    for (int k = 0; k < 8; ++k) {
        const int c = tid + k*256;
        outr[c] = (vals[k] - mean)*inv*gamma[c] + beta[c];
    }
}

// ============================================================
// Launch
// ============================================================
extern "C" void kernel_launch(void* const* d_in, const int* in_sizes, int n_in,
                              void* d_out, int out_size)
{
    const float* x     = (const float*)d_in[0];
    const float* Wq    = (const float*)d_in[1];
    const float* bq    = (const float*)d_in[2];
    const float* Wk    = (const float*)d_in[3];
    const float* bk    = (const float*)d_in[4];
    const float* Wv    = (const float*)d_in[5];
    const float* bv    = (const float*)d_in[6];
    const float* Wo    = (const float*)d_in[7];
    const float* bo    = (const float*)d_in[8];
    const float* gamma = (const float*)d_in[9];
    const float* beta  = (const float*)d_in[10];
    float* out = (float*)d_out;

    float *Q, *K, *V, *CTX, *Y;
    cudaGetSymbolAddress((void**)&Q,   g_Q);
    cudaGetSymbolAddress((void**)&K,   g_K);
    cudaGetSymbolAddress((void**)&V,   g_V);
    cudaGetSymbolAddress((void**)&CTX, g_CTX);
    cudaGetSymbolAddress((void**)&Y,   g_Y);

    const dim3 blk(256);

    // QKV projections
    sgemm_bias<<<dim3(HE/128,  ML/128), blk>>>(x, Wq, bq, Q, ML, HE,  DD);
    sgemm_bias<<<dim3(KVE/128, ML/128), blk>>>(x, Wk, bk, K, ML, KVE, DD);
    sgemm_bias<<<dim3(KVE/128, ML/128), blk>>>(x, Wv, bv, V, ML, KVE, DD);

    // causal GQA flash attention
    const size_t fl_smem = (size_t)FL_SMEM_FLOATS * sizeof(float);
    cudaFuncSetAttribute(flash_kernel, cudaFuncAttributeMaxDynamicSharedMemorySize,
                         (int)fl_smem);
    flash_kernel<<<dim3(LL/64, BB*HH), blk, fl_smem>>>(Q, K, V, CTX);

    // output projection (pre-GELU)
    sgemm_bias<<<dim3(DD/128, ML/128), blk>>>(CTX, Wo, bo, Y, ML, DD, HE);

    // GELU + residual + LayerNorm
    epilogue_ln<<<ML, 256>>>(x, Y, gamma, beta, out);
}

// round 3
// speedup vs baseline: 1.0019x; 1.0006x over previous
#include <cuda_runtime.h>
#include <math.h>

// Problem constants
#define BB   2
#define LL   2048
#define DD   2048
#define HH   16
#define KVH  4
#define EE   128
#define ML   (BB*LL)        // 4096 rows total
#define HE   (HH*EE)        // 2048
#define KVE  (KVH*EE)       // 512

// -------- scratch (device globals; no allocation allowed) --------
__device__ float g_Q[ML*HE];      // [B*L, H*E]
__device__ float g_K[ML*KVE];     // [B*L, KV*E]
__device__ float g_V[ML*KVE];     // [B*L, KV*E]
__device__ float g_CTX[ML*HE];    // attention output
__device__ float g_Y[ML*DD];      // pre-GELU O-proj output

// ============================================================
// SGEMM: C[M,N] = A[M,K] @ B[K,N] + bias[N]   (row-major all)
// 128x128 block tile, BK=8, 256 threads, 8x8 per thread.
// Requires M%128==0, N%128==0, K%8==0 (true for all our shapes).
// ============================================================
__global__ __launch_bounds__(256)
void sgemm_bias(const float* __restrict__ A, const float* __restrict__ B,
                const float* __restrict__ bias, float* __restrict__ C,
                int M, int N, int K)
{
    __shared__ float As[8][128];   // transposed A tile: As[k][m]
    __shared__ float Bs[8][128];   // Bs[k][n]

    const int tid = threadIdx.x;
    const int bx = blockIdx.x, by = blockIdx.y;
    const int tx = tid & 15, ty = tid >> 4;

    const int a_r = tid >> 1, a_c = (tid & 1) * 4;      // A: 128 rows x 8 cols (float4)
    const int b_r = tid >> 5, b_c = (tid & 31) * 4;     // B: 8 rows x 128 cols (float4)

    const float* Ag = A + ((size_t)(by*128 + a_r))*K + a_c;
    const float* Bg = B + (size_t)b_r*N + bx*128 + b_c;

    float acc[8][8];
    #pragma unroll
    for (int a = 0; a < 8; a++)
        #pragma unroll
        for (int b2 = 0; b2 < 8; b2++) acc[a][b2] = 0.f;

    for (int k0 = 0; k0 < K; k0 += 8) {
        float4 av = *(const float4*)(Ag + k0);
        As[a_c+0][a_r] = av.x;
        As[a_c+1][a_r] = av.y;
        As[a_c+2][a_r] = av.z;
        As[a_c+3][a_r] = av.w;
        *(float4*)&Bs[b_r][b_c] = *(const float4*)(Bg + (size_t)k0*N);
        __syncthreads();

        #pragma unroll
        for (int k = 0; k < 8; ++k) {
            float ar[8], br[8];
            *(float4*)(ar)   = *(float4*)&As[k][ty*8];
            *(float4*)(ar+4) = *(float4*)&As[k][ty*8+4];
            *(float4*)(br)   = *(float4*)&Bs[k][tx*8];
            *(float4*)(br+4) = *(float4*)&Bs[k][tx*8+4];
            #pragma unroll
            for (int a = 0; a < 8; a++)
                #pragma unroll
                for (int b2 = 0; b2 < 8; b2++)
                    acc[a][b2] += ar[a]*br[b2];
        }
        __syncthreads();
    }

    #pragma unroll
    for (int a = 0; a < 8; a++) {
        const int row = by*128 + ty*8 + a;
        #pragma unroll
        for (int b2 = 0; b2 < 8; b2 += 4) {
            const int col = bx*128 + tx*8 + b2;
            float4 o;
            o.x = acc[a][b2+0] + bias[col+0];
            o.y = acc[a][b2+1] + bias[col+1];
            o.z = acc[a][b2+2] + bias[col+2];
            o.w = acc[a][b2+3] + bias[col+3];
            *(float4*)(C + (size_t)row*N + col) = o;
        }
    }
}

// ============================================================
// Flash attention (causal, GQA): per block = one (b,h) x 64-query tile.
// Br=Bc=64, E=128. Online softmax, O in registers (4 rows x 8 cols / thread).
// ============================================================
#define FL_SMEM_FLOATS (64*128 + 128*68 + 64*128 + 64*68 + 192)

__global__ __launch_bounds__(256)
void flash_kernel(const float* __restrict__ Q, const float* __restrict__ K,
                  const float* __restrict__ V, float* __restrict__ ctx)
{
    extern __shared__ float sm[];
    float* Qs  = sm;                  // [64][128]  scaled Q
    float* Kst = Qs  + 64*128;        // [128][68]  K transposed (e-major), padded
    float* Vs  = Kst + 128*68;        // [64][128]
    float* Ss  = Vs  + 64*128;        // [64][68]   scores / probabilities
    float* mrow = Ss + 64*68;         // [64]
    float* lrow = mrow + 64;          // [64]
    float* arow = lrow + 64;          // [64]

    const int tid = threadIdx.x;
    const int bh  = blockIdx.y;
    const int b   = bh / HH, h = bh % HH;
    const int kv  = h % KVH;                 // GQA: head h reads kv-head h%KV
    const int qb  = blockIdx.x * 64;
    const float scale = 0.08838834764831845f;   // 1/sqrt(128)

    // load Q tile (pre-scaled)
    {
        const float* Qg = Q + ((size_t)(b*LL + qb))*HE + h*EE;
        for (int t = tid; t < 64*32; t += 256) {
            int r = t >> 5, c4 = (t & 31) << 2;
            float4 v = *(const float4*)(Qg + (size_t)r*HE + c4);
            v.x *= scale; v.y *= scale; v.z *= scale; v.w *= scale;
            *(float4*)(Qs + r*128 + c4) = v;
        }
    }
    if (tid < 64) { mrow[tid] = -INFINITY; lrow[tid] = 0.f; }

    float O[4][8];
    #pragma unroll
    for (int a = 0; a < 4; a++)
        #pragma unroll
        for (int e = 0; e < 8; e++) O[a][e] = 0.f;

    const int i = tid >> 4, j = tid & 15;   // 16x16 thread grid
    const int r0 = i*4;                     // 4 query rows per thread
    const int c0 = j*4;                     // 4 key cols (S phase)
    const int e0 = j*8;                     // 8 head dims (O phase)

    const int ntiles = qb/64 + 1;           // causal
    for (int tkv = 0; tkv < ntiles; ++tkv) {
        const int kb = tkv * 64;
        __syncthreads();   // protect smem reuse across iterations (and Q load, 1st iter)

        // load K (transposed into Kst[e][c]) and V (row-major)
        const float* Kg = K + ((size_t)(b*LL + kb))*KVE + kv*EE;
        const float* Vg = V + ((size_t)(b*LL + kb))*KVE + kv*EE;
        for (int t = tid; t < 64*32; t += 256) {
            int r = t >> 5, c4 = (t & 31) << 2;
            float4 vk = *(const float4*)(Kg + (size_t)r*KVE + c4);
            Kst[(c4+0)*68 + r] = vk.x;
            Kst[(c4+1)*68 + r] = vk.y;
            Kst[(c4+2)*68 + r] = vk.z;
            Kst[(c4+3)*68 + r] = vk.w;
            *(float4*)(Vs + r*128 + c4) = *(const float4*)(Vg + (size_t)r*KVE + c4);
        }
        __syncthreads();

        // S = (Q*scale) @ K^T : each thread computes a 4x4 block
        float acc[4][4];
        #pragma unroll
        for (int a = 0; a < 4; a++)
            #pragma unroll
            for (int c = 0; c < 4; c++) acc[a][c] = 0.f;

        #pragma unroll 4
        for (int e = 0; e < 128; ++e) {
            const float q0 = Qs[(r0+0)*128 + e];
            const float q1 = Qs[(r0+1)*128 + e];
            const float q2 = Qs[(r0+2)*128 + e];
            const float q3 = Qs[(r0+3)*128 + e];
            const float4 kvv = *(const float4*)(Kst + e*68 + c0);
            acc[0][0] += q0*kvv.x; acc[0][1] += q0*kvv.y; acc[0][2] += q0*kvv.z; acc[0][3] += q0*kvv.w;
            acc[1][0] += q1*kvv.x; acc[1][1] += q1*kvv.y; acc[1][2] += q1*kvv.z; acc[1][3] += q1*kvv.w;
            acc[2][0] += q2*kvv.x; acc[2][1] += q2*kvv.y; acc[2][2] += q2*kvv.z; acc[2][3] += q2*kvv.w;
            acc[3][0] += q3*kvv.x; acc[3][1] += q3*kvv.y; acc[3][2] += q3*kvv.z; acc[3][3] += q3*kvv.w;
        }

        const bool diag = (kb == qb);
        #pragma unroll
        for (int a = 0; a < 4; a++)
            #pragma unroll
            for (int c = 0; c < 4; c++) {
                float v = acc[a][c];
                if (diag && (c0 + c) > (r0 + a)) v = -1e30f;
                Ss[(r0+a)*68 + c0 + c] = v;
            }
        __syncthreads();

        // online softmax per row (64 threads)
        if (tid < 64) {
            const int r = tid;
            float mx = -1e30f;
            #pragma unroll 8
            for (int c = 0; c < 64; ++c) mx = fmaxf(mx, Ss[r*68 + c]);
            const float mold = mrow[r];
            const float mnew = fmaxf(mold, mx);
            const float al   = __expf(mold - mnew);   // 0 on first tile
            float s = 0.f;
            #pragma unroll 8
            for (int c = 0; c < 64; ++c) {
                float p = __expf(Ss[r*68 + c] - mnew);
                Ss[r*68 + c] = p;
                s += p;
            }
            mrow[r] = mnew;
            lrow[r] = lrow[r]*al + s;
            arow[r] = al;
        }
        __syncthreads();

        // O = O*alpha + P @ V
        const float al0 = arow[r0+0], al1 = arow[r0+1], al2 = arow[r0+2], al3 = arow[r0+3];
        #pragma unroll
        for (int e = 0; e < 8; e++) {
            O[0][e] *= al0; O[1][e] *= al1; O[2][e] *= al2; O[3][e] *= al3;
        }
        #pragma unroll 2
        for (int c = 0; c < 64; ++c) {
            const float p0 = Ss[(r0+0)*68 + c];
            const float p1 = Ss[(r0+1)*68 + c];
            const float p2 = Ss[(r0+2)*68 + c];
            const float p3 = Ss[(r0+3)*68 + c];
            const float4 va = *(const float4*)(Vs + c*128 + e0);
            const float4 vb = *(const float4*)(Vs + c*128 + e0 + 4);
            O[0][0]+=p0*va.x; O[0][1]+=p0*va.y; O[0][2]+=p0*va.z; O[0][3]+=p0*va.w;
            O[0][4]+=p0*vb.x; O[0][5]+=p0*vb.y; O[0][6]+=p0*vb.z; O[0][7]+=p0*vb.w;
            O[1][0]+=p1*va.x; O[1][1]+=p1*va.y; O[1][2]+=p1*va.z; O[1][3]+=p1*va.w;
            O[1][4]+=p1*vb.x; O[1][5]+=p1*vb.y; O[1][6]+=p1*vb.z; O[1][7]+=p1*vb.w;
            O[2][0]+=p2*va.x; O[2][1]+=p2*va.y; O[2][2]+=p2*va.z; O[2][3]+=p2*va.w;
            O[2][4]+=p2*vb.x; O[2][5]+=p2*vb.y; O[2][6]+=p2*vb.z; O[2][7]+=p2*vb.w;
            O[3][0]+=p3*va.x; O[3][1]+=p3*va.y; O[3][2]+=p3*va.z; O[3][3]+=p3*va.w;
            O[3][4]+=p3*vb.x; O[3][5]+=p3*vb.y; O[3][6]+=p3*vb.z; O[3][7]+=p3*vb.w;
        }
    }

    // write out ctx (divide by l)
    float* Cg = ctx + ((size_t)(b*LL + qb))*HE + h*EE;
    #pragma unroll
    for (int a = 0; a < 4; a++) {
        const float inv = 1.f / lrow[r0+a];
        float4 oa, ob;
        oa.x = O[a][0]*inv; oa.y = O[a][1]*inv; oa.z = O[a][2]*inv; oa.w = O[a][3]*inv;
        ob.x = O[a][4]*inv; ob.y = O[a][5]*inv; ob.z = O[a][6]*inv; ob.w = O[a][7]*inv;
        *(float4*)(Cg + (size_t)(r0+a)*HE + e0)     = oa;
        *(float4*)(Cg + (size_t)(r0+a)*HE + e0 + 4) = ob;
    }
}

// ============================================================
// Epilogue: out = LayerNorm(x + gelu_erf(ypre)) * gamma + beta
// One block per row, 256 threads, 8 elements/thread (D=2048).
// ============================================================
__global__ __launch_bounds__(256)
void epilogue_ln(const float* __restrict__ x, const float* __restrict__ ypre,
                 const float* __restrict__ gamma, const float* __restrict__ beta,
                 float* __restrict__ out)
{
    const int row = blockIdx.x;
    const int tid = threadIdx.x;
    const float* xr = x    + (size_t)row*DD;
    const float* yr = ypre + (size_t)row*DD;
    float* outr     = out  + (size_t)row*DD;

    float vals[8];
    float s = 0.f, s2 = 0.f;
    #pragma unroll
    for (int k = 0; k < 8; ++k) {
        const int c = tid + k*256;
        const float v = yr[c];
        const float g = 0.5f*v*(1.f + erff(v*0.70710678118654752f));
        const float r = xr[c] + g;
        vals[k] = r;
        s += r; s2 += r*r;
    }

    // block reduce (8 warps)
    __shared__ float red[2][8];
    #pragma unroll
    for (int off = 16; off > 0; off >>= 1) {
        s  += __shfl_down_sync(0xFFFFFFFFu, s,  off);
        s2 += __shfl_down_sync(0xFFFFFFFFu, s2, off);
    }
    if ((tid & 31) == 0) { red[0][tid>>5] = s; red[1][tid>>5] = s2; }
    __syncthreads();
    float ts = 0.f, ts2 = 0.f;
    #pragma unroll
    for (int w = 0; w < 8; w++) { ts += red[0][w]; ts2 += red[1][w]; }

    const float mean = ts * (1.f/2048.f);
    const float var  = ts2 * (1.f/2048.f) - mean*mean;
    const float inv  = rsqrtf(var + 1e-5f);

    #pragma unroll
    for (int k = 0; k < 8; ++k) {
        const int c = tid + k*256;
        outr[c] = (vals[k] - mean)*inv*gamma[c] + beta[c];
    }
}

// ============================================================
// Launch
// ============================================================
extern "C" void kernel_launch(void* const* d_in, const int* in_sizes, int n_in,
                              void* d_out, int out_size)
{
    const float* x     = (const float*)d_in[0];
    const float* Wq    = (const float*)d_in[1];
    const float* bq    = (const float*)d_in[2];
    const float* Wk    = (const float*)d_in[3];
    const float* bk    = (const float*)d_in[4];
    const float* Wv    = (const float*)d_in[5];
    const float* bv    = (const float*)d_in[6];
    const float* Wo    = (const float*)d_in[7];
    const float* bo    = (const float*)d_in[8];
    const float* gamma = (const float*)d_in[9];
    const float* beta  = (const float*)d_in[10];
    float* out = (float*)d_out;

    float *Q, *K, *V, *CTX, *Y;
    cudaGetSymbolAddress((void**)&Q,   g_Q);
    cudaGetSymbolAddress((void**)&K,   g_K);
    cudaGetSymbolAddress((void**)&V,   g_V);
    cudaGetSymbolAddress((void**)&CTX, g_CTX);
    cudaGetSymbolAddress((void**)&Y,   g_Y);

    const dim3 blk(256);

    // QKV projections
    sgemm_bias<<<dim3(HE/128,  ML/128), blk>>>(x, Wq, bq, Q, ML, HE,  DD);
    sgemm_bias<<<dim3(KVE/128, ML/128), blk>>>(x, Wk, bk, K, ML, KVE, DD);
    sgemm_bias<<<dim3(KVE/128, ML/128), blk>>>(x, Wv, bv, V, ML, KVE, DD);

    // causal GQA flash attention
    const size_t fl_smem = (size_t)FL_SMEM_FLOATS * sizeof(float);
    cudaFuncSetAttribute(flash_kernel, cudaFuncAttributeMaxDynamicSharedMemorySize,
                         (int)fl_smem);
    flash_kernel<<<dim3(LL/64, BB*HH), blk, fl_smem>>>(Q, K, V, CTX);

    // output projection (pre-GELU)
    sgemm_bias<<<dim3(DD/128, ML/128), blk>>>(CTX, Wo, bo, Y, ML, DD, HE);

    // GELU + residual + LayerNorm
    epilogue_ln<<<ML, 256>>>(x, Y, gamma, beta, out);
}